// round 15
// baseline (speedup 1.0000x reference)
#include <cuda_runtime.h>
#include <cuda_fp16.h>
#include <cuda_fp8.h>
#include <cstdint>

#define RANK  200
#define NNZ   500000
#define N_ENT 200000
#define N_REL 500
#define RV4   (RANK / 4)   // 50 float4 per row (fp32 path)

#define ROW_B   224        // padded fp8 row bytes
#define ROW_U2  28         // uint2 groups per padded row
#define DATA_U2 25         // uint2 groups holding real data
#define ROW_U4  14         // uint4 chunks per padded row (13 hold data)

#define SCALE_A 256.0f
#define SCALE_B 16.0f
#define INV_SCALE (1.0f / (SCALE_A * SCALE_A * SCALE_B))   // 2^-20, exact

// Fused-kernel block partition (Bresenham proportional interleave).
#define NA_BLOCKS 15625    // pass_a: 32 nnz/block (8 warps x 4 nnz) -> exact
#define NB_BLOCKS 25063    // pass_b: 8 rows/block over N_ENT+N_REL=200500
#define TOT_BLOCKS (NA_BLOCKS + NB_BLOCKS)

// Scratch (__device__ globals: zero-initialized at load; conv fully rewrites
// the mirrors, winner slots are self-reset by the consumer, so every
// invocation — correctness run and each graph replay — starts identically).
__device__ int g_win_a[N_ENT];   // winner key: n+1 (subj) or n+1+NNZ (obj); 0 = none
__device__ int g_win_b[N_REL];   // winner key: n+1; 0 = none
__device__ __align__(16) uint8_t g_a8[(size_t)N_ENT * ROW_B]; // e4m3(a*256), 44.8 MB
__device__ __align__(16) uint8_t g_b8[(size_t)N_REL * ROW_B]; // e4m3(b*16), 112 KB

#define NAG (N_ENT * ROW_U2)
#define NBG (N_REL * ROW_U2)

// ---------------------------------------------------------------------------
// Kernel 1: fp8 mirror build + winner races, fused. The winner atomics run
// on the UNSORTED nnz stream (addresses spread across 200K / 500 slots
// concurrently — the pattern measured free in R2). Winners depend only on
// coo, so they are ready before the fused compute kernel.
// ---------------------------------------------------------------------------
__device__ __forceinline__ uint32_t pack4_e4m3(float4 v, float s) {
    __nv_fp8x2_storage_t lo = __nv_cvt_float2_to_fp8x2(
        make_float2(v.x * s, v.y * s), __NV_SATFINITE, __NV_E4M3);
    __nv_fp8x2_storage_t hi = __nv_cvt_float2_to_fp8x2(
        make_float2(v.z * s, v.w * s), __NV_SATFINITE, __NV_E4M3);
    return (uint32_t)lo | ((uint32_t)hi << 16);
}

__global__ void __launch_bounds__(256) conv_win_kernel(
    const float* __restrict__ a,
    const float* __restrict__ b,
    const int*   __restrict__ coo)
{
    int i = blockIdx.x * blockDim.x + threadIdx.x;
    if (i < NAG) {
        int row = i / ROW_U2;
        int idx = i - row * ROW_U2;
        uint2 p = make_uint2(0u, 0u);
        if (idx < DATA_U2) {
            const float4* src = (const float4*)a + (size_t)row * RV4 + 2 * idx;
            p.x = pack4_e4m3(__ldcs(src),     SCALE_A);
            p.y = pack4_e4m3(__ldcs(src + 1), SCALE_A);
        }
        ((uint2*)g_a8)[i] = p;
    } else if (i < NAG + NBG) {
        int j = i - NAG;
        int row = j / ROW_U2;
        int idx = j - row * ROW_U2;
        uint2 p = make_uint2(0u, 0u);
        if (idx < DATA_U2) {
            const float4* src = (const float4*)b + (size_t)row * RV4 + 2 * idx;
            p.x = pack4_e4m3(__ldcs(src),     SCALE_B);
            p.y = pack4_e4m3(__ldcs(src + 1), SCALE_B);
        }
        ((uint2*)g_b8)[j] = p;
    } else if (i < NAG + NBG + NNZ) {
        // Winner races. Key encoding reproduces XLA sequential-scatter
        // semantics: obj writes (.set applied second) beat subj writes
        // (key n+1+NNZ vs n+1); within a class, higher nnz index wins.
        int n = i - NAG - NBG;
        int s = __ldg(coo + 3 * n + 0);
        int r = __ldg(coo + 3 * n + 1);
        int o = __ldg(coo + 3 * n + 2);
        atomicMax(&g_win_a[s], n + 1);
        atomicMax(&g_win_a[o], n + 1 + NNZ);
        atomicMax(&g_win_b[r], n + 1);
    }
}

// fp8x2 (low 16 bits) -> half2
__device__ __forceinline__ __half2 cvt8(uint32_t u) {
    __half2_raw hr = __nv_cvt_fp8x2_to_halfraw2((__nv_fp8x2_storage_t)u, __NV_E4M3);
    return *(__half2*)&hr;
}

// Triple product of 8 fp8 per operand (uint2) into half2 accumulator.
__device__ __forceinline__ __half2 tp8(__half2 acc, uint2 A, uint2 B, uint2 C) {
    acc = __hfma2(__hmul2(cvt8(A.x & 0xFFFFu), cvt8(B.x & 0xFFFFu)),
                  cvt8(C.x & 0xFFFFu), acc);
    acc = __hfma2(__hmul2(cvt8(A.x >> 16), cvt8(B.x >> 16)),
                  cvt8(C.x >> 16), acc);
    acc = __hfma2(__hmul2(cvt8(A.y & 0xFFFFu), cvt8(B.y & 0xFFFFu)),
                  cvt8(C.y & 0xFFFFu), acc);
    acc = __hfma2(__hmul2(cvt8(A.y >> 16), cvt8(B.y >> 16)),
                  cvt8(C.y >> 16), acc);
    return acc;
}

// 16-fp8 triple product (uint4 chunks) into half2 accumulator.
__device__ __forceinline__ __half2 tp16(__half2 acc, uint4 A, uint4 B, uint4 C) {
    acc = tp8(acc, make_uint2(A.x, A.y), make_uint2(B.x, B.y), make_uint2(C.x, C.y));
    acc = tp8(acc, make_uint2(A.z, A.w), make_uint2(B.z, B.w), make_uint2(C.z, C.w));
    return acc;
}

// ---------------------------------------------------------------------------
// pass_a block work: 8 warps x 4 nnz (8-lane segments). Computes ONLY loss
// (deriv is recomputed by pass_b; winners already done in conv_win).
// ---------------------------------------------------------------------------
__device__ __forceinline__ void pass_a_work(
    int ablk,
    const int*   __restrict__ coo,
    const float* __restrict__ vals,
    float*       __restrict__ loss)
{
    int gw   = ablk * 8 + (threadIdx.x >> 5);   // < 125000 exact
    int lane = threadIdx.x & 31;
    int sg   = lane >> 3;
    int sl   = lane & 7;
    int n    = 4 * gw + sg;                     // < NNZ exact

    int c = (sl < 3) ? __ldg(coo + 3 * n + sl) : 0;
    int base = sg << 3;
    int s = __shfl_sync(0xffffffffu, c, base + 0);
    int r = __shfl_sync(0xffffffffu, c, base + 1);
    int o = __shfl_sync(0xffffffffu, c, base + 2);

    float val = __ldg(vals + n);

    const uint4* a0 = (const uint4*)(g_a8 + (size_t)s * ROW_B);
    const uint4* b1 = (const uint4*)(g_b8 + (size_t)r * ROW_B);
    const uint4* a2 = (const uint4*)(g_a8 + (size_t)o * ROW_B);

    const uint4 Z = make_uint4(0u, 0u, 0u, 0u);
    bool hi = (sl < 5);            // chunks 8..12 (13 data chunks total)

    uint4 x0 = __ldcg(a0 + sl);
    uint4 z0 = __ldcg(a2 + sl);
    uint4 y0 = __ldg (b1 + sl);
    uint4 x1 = hi ? __ldcg(a0 + 8 + sl) : Z;
    uint4 z1 = hi ? __ldcg(a2 + 8 + sl) : Z;
    uint4 y1 = hi ? __ldg (b1 + 8 + sl) : Z;

    __half2 acc = __float2half2_rn(0.0f);
    acc = tp16(acc, x0, y0, z0);
    acc = tp16(acc, x1, y1, z1);
    float2 f = __half22float2(acc);
    float sum = f.x + f.y;

    #pragma unroll
    for (int off = 4; off; off >>= 1)
        sum += __shfl_down_sync(0xffffffffu, sum, off, 8);

    if (sl == 0) {
        float diff = sum * INV_SCALE - val;
        __stcs(loss + n, diff * diff);
    }
}

// ---------------------------------------------------------------------------
// pass_b block work: 8 warps, one output row each. Winner rows recompute
// their deriv locally from the fp8 mirrors (32-lane dot, same ~7e-7 accuracy
// as the loss path), then gather the two fp32 rows and write d*x*y.
// Self-resets winner slots for the next invocation.
// ---------------------------------------------------------------------------
__device__ __forceinline__ void pass_b_work(
    int bblk,
    const int*   __restrict__ coo,
    const float* __restrict__ vals,
    const float* __restrict__ a,
    const float* __restrict__ b,
    float*       __restrict__ grad_a,
    float*       __restrict__ grad_b)
{
    int warp = bblk * 8 + (threadIdx.x >> 5);
    int lane = threadIdx.x & 31;
    if (warp >= N_ENT + N_REL) return;

    float4* out;
    int k, n = 0;
    bool is_ent = (warp < N_ENT);

    if (is_ent) {
        out = (float4*)(grad_a + (size_t)warp * RANK);
        k = g_win_a[warp];
        if (k > 0 && lane == 0) g_win_a[warp] = 0;   // self-reset
    } else {
        out = (float4*)(grad_b + (size_t)(warp - N_ENT) * RANK);
        k = g_win_b[warp - N_ENT];
        if (k > 0 && lane == 0) g_win_b[warp - N_ENT] = 0;
    }

    if (k <= 0) {
        float4 z = make_float4(0.f, 0.f, 0.f, 0.f);
        #pragma unroll
        for (int it = 0; it < 2; it++) {
            int j = lane + it * 32;
            if (j < RV4) __stcs(out + j, z);
        }
        return;
    }

    bool is_obj = is_ent && (k > NNZ);
    n = is_obj ? (k - 1 - NNZ) : (k - 1);

    int s = __ldg(coo + 3 * n + 0);
    int r = __ldg(coo + 3 * n + 1);
    int o = __ldg(coo + 3 * n + 2);

    // Recompute deriv: fp8 dot over 25 active lanes, full-warp reduce.
    const uint2* pa0 = (const uint2*)(g_a8 + (size_t)s * ROW_B);
    const uint2* pb1 = (const uint2*)(g_b8 + (size_t)r * ROW_B);
    const uint2* pa2 = (const uint2*)(g_a8 + (size_t)o * ROW_B);
    bool act = (lane < DATA_U2);
    uint2 Zu = make_uint2(0u, 0u);
    uint2 A  = act ? __ldcg(pa0 + lane) : Zu;
    uint2 Bv = act ? __ldg (pb1 + lane) : Zu;
    uint2 C  = act ? __ldcg(pa2 + lane) : Zu;
    __half2 hacc = __float2half2_rn(0.0f);
    hacc = tp8(hacc, A, Bv, C);
    float2 hf = __half22float2(hacc);
    float sum = hf.x + hf.y;
    #pragma unroll
    for (int off = 16; off; off >>= 1)
        sum += __shfl_xor_sync(0xffffffffu, sum, off);
    float d = 2.0f * (sum * INV_SCALE - __ldg(vals + n));

    // Select the two fp32 factor rows.
    const float4* x;   // b-row where applicable (L1 path)
    const float4* y;
    bool x_is_b;
    if (is_ent) {
        x = (const float4*)(b + (size_t)r * RANK); x_is_b = true;
        y = (const float4*)(a + (size_t)(is_obj ? s : o) * RANK);
        // obj winner: g_c = d * a0 * b1 ; subj winner: g_a = d * b1 * a2
    } else {
        x = (const float4*)(a + (size_t)s * RANK); x_is_b = false;
        y = (const float4*)(a + (size_t)o * RANK);   // g_b = d * a0 * a2
    }

    #pragma unroll
    for (int it = 0; it < 2; it++) {
        int j = lane + it * 32;
        if (j < RV4) {
            float4 u = x_is_b ? __ldg(x + j) : __ldcg(x + j);
            float4 v = __ldcg(y + j);
            float4 w = make_float4(d * u.x * v.x, d * u.y * v.y,
                                   d * u.z * v.z, d * u.w * v.w);
            __stcs(out + j, w);
        }
    }
}

// ---------------------------------------------------------------------------
// Fused kernel: pass_a and pass_b are independent (winners precomputed,
// deriv recomputed locally), so their blocks share one grid, interleaved
// proportionally (Bresenham) so each wave carries both workloads — pass_a's
// latency-bound gathers overlap pass_b's DRAM-bound streaming writes.
// ---------------------------------------------------------------------------
__global__ void __launch_bounds__(256) fused_kernel(
    const int*   __restrict__ coo,
    const float* __restrict__ vals,
    const float* __restrict__ a,
    const float* __restrict__ b,
    float*       __restrict__ loss,
    float*       __restrict__ grad_a,
    float*       __restrict__ grad_b)
{
    int bid = blockIdx.x;
    long long t = (long long)bid * NA_BLOCKS;
    int lo = (int)(t / TOT_BLOCKS);
    int hi = (int)((t + NA_BLOCKS) / TOT_BLOCKS);
    if (hi > lo)
        pass_a_work(lo, coo, vals, loss);
    else
        pass_b_work(bid - hi, coo, vals, a, b, grad_a, grad_b);
}

// ---------------------------------------------------------------------------
// Launch. Inputs (metadata order): coo_ns int32 [NNZ,3], vals_ns f32 [NNZ],
// a f32 [N_ENT,RANK], b f32 [N_REL,RANK].
// Output: loss[NNZ] | grad_a[N_ENT*RANK] | grad_b[N_REL*RANK]  (f32).
// ---------------------------------------------------------------------------
extern "C" void kernel_launch(void* const* d_in, const int* in_sizes, int n_in,
                              void* d_out, int out_size)
{
    const int*   coo  = (const int*)d_in[0];
    const float* vals = (const float*)d_in[1];
    const float* a    = (const float*)d_in[2];
    const float* b    = (const float*)d_in[3];

    float* out    = (float*)d_out;
    float* loss   = out;
    float* grad_a = out + NNZ;
    float* grad_b = out + NNZ + (size_t)N_ENT * RANK;

    {   // fp8 mirror build + winner races
        int total = NAG + NBG + NNZ;
        conv_win_kernel<<<(total + 255) / 256, 256>>>(a, b, coo);
    }
    // fused loss + gradient kernel
    fused_kernel<<<TOT_BLOCKS, 256>>>(coo, vals, a, b, loss, grad_a, grad_b);
}

// round 16
// speedup vs baseline: 1.0412x; 1.0412x over previous
#include <cuda_runtime.h>
#include <cuda_fp16.h>
#include <cuda_fp8.h>
#include <cstdint>

#define RANK  200
#define NNZ   500000
#define N_ENT 200000
#define N_REL 500
#define RV4   (RANK / 4)   // 50 float4 per row (fp32 path)

#define ROW_B   224        // padded fp8 row bytes
#define ROW_U2  28         // uint2 groups per padded row
#define DATA_U2 25         // uint2 groups holding real data

#define SCALE_A 256.0f
#define SCALE_B 16.0f
#define INV_SCALE (1.0f / (SCALE_A * SCALE_A * SCALE_B))   // 2^-20, exact

// Fused-kernel block partition (Bresenham proportional interleave).
#define NA_BLOCKS 15625    // pass_a: 32 nnz/block (8 warps x 4 nnz) -> exact
#define NB_BLOCKS 25063    // pass_b: 8 rows/block over N_ENT+N_REL=200500
#define TOT_BLOCKS (NA_BLOCKS + NB_BLOCKS)

// conv kernel geometry
#define NAG (N_ENT * ROW_U2)          // 5,600,000 conv threads for a
#define NBG (N_REL * ROW_U2)          // 14,000 conv threads for b
#define CONV_BLOCKS ((NAG + NBG + 255) / 256)   // 21,930
#define WIN_PER_BLOCK 23              // 21,930 * 23 = 504,390 >= NNZ

// Scratch (__device__ globals: zero-initialized at load; conv fully rewrites
// the mirrors, winner slots are self-reset by the consumer, so every
// invocation — correctness run and each graph replay — starts identically).
__device__ int g_win_a[N_ENT];   // winner key: n+1 (subj) or n+1+NNZ (obj); 0 = none
__device__ int g_win_b[N_REL];   // winner key: n+1; 0 = none
__device__ __align__(16) uint8_t g_a8[(size_t)N_ENT * ROW_B]; // e4m3(a*256), 44.8 MB
__device__ __align__(16) uint8_t g_b8[(size_t)N_REL * ROW_B]; // e4m3(b*16), 112 KB

// ---------------------------------------------------------------------------
// Kernel 1: fp8 mirror build + winner races, with the 1.5M winner atomics
// SPREAD UNIFORMLY across all conv blocks (R15 post-mortem: concentrating
// them in a tail cost ~70us of exposed atomic-throughput time; spread across
// the DRAM-bound conv duration they overlap). Lanes 0-22 of each block's
// warp 0 each own one nnz: 3 LDG + 3 fire-and-forget RED.MAX issued BEFORE
// the conv work so they fly during the conv memory stalls.
// Winner-key encoding reproduces XLA sequential-scatter semantics: obj
// writes (.set applied second) beat subj writes (key n+1+NNZ vs n+1);
// within a class, higher nnz index wins (last update wins).
// ---------------------------------------------------------------------------
__device__ __forceinline__ uint32_t pack4_e4m3(float4 v, float s) {
    __nv_fp8x2_storage_t lo = __nv_cvt_float2_to_fp8x2(
        make_float2(v.x * s, v.y * s), __NV_SATFINITE, __NV_E4M3);
    __nv_fp8x2_storage_t hi = __nv_cvt_float2_to_fp8x2(
        make_float2(v.z * s, v.w * s), __NV_SATFINITE, __NV_E4M3);
    return (uint32_t)lo | ((uint32_t)hi << 16);
}

__global__ void __launch_bounds__(256) conv_win_kernel(
    const float* __restrict__ a,
    const float* __restrict__ b,
    const int*   __restrict__ coo)
{
    // --- winner races, spread: 23 nnz per block, issued first ---
    {
        int n = blockIdx.x * WIN_PER_BLOCK + threadIdx.x;
        if (threadIdx.x < WIN_PER_BLOCK && n < NNZ) {
            int s = __ldg(coo + 3 * n + 0);
            int r = __ldg(coo + 3 * n + 1);
            int o = __ldg(coo + 3 * n + 2);
            atomicMax(&g_win_a[s], n + 1);        // subj class
            atomicMax(&g_win_a[o], n + 1 + NNZ);  // obj class (beats subj)
            atomicMax(&g_win_b[r], n + 1);
        }
    }

    // --- fp8 mirror build ---
    int i = blockIdx.x * blockDim.x + threadIdx.x;
    if (i < NAG) {
        int row = i / ROW_U2;
        int idx = i - row * ROW_U2;
        uint2 p = make_uint2(0u, 0u);
        if (idx < DATA_U2) {
            const float4* src = (const float4*)a + (size_t)row * RV4 + 2 * idx;
            p.x = pack4_e4m3(__ldcs(src),     SCALE_A);
            p.y = pack4_e4m3(__ldcs(src + 1), SCALE_A);
        }
        ((uint2*)g_a8)[i] = p;
    } else if (i < NAG + NBG) {
        int j = i - NAG;
        int row = j / ROW_U2;
        int idx = j - row * ROW_U2;
        uint2 p = make_uint2(0u, 0u);
        if (idx < DATA_U2) {
            const float4* src = (const float4*)b + (size_t)row * RV4 + 2 * idx;
            p.x = pack4_e4m3(__ldcs(src),     SCALE_B);
            p.y = pack4_e4m3(__ldcs(src + 1), SCALE_B);
        }
        ((uint2*)g_b8)[j] = p;
    }
}

// fp8x2 (low 16 bits) -> half2
__device__ __forceinline__ __half2 cvt8(uint32_t u) {
    __half2_raw hr = __nv_cvt_fp8x2_to_halfraw2((__nv_fp8x2_storage_t)u, __NV_E4M3);
    return *(__half2*)&hr;
}

// Triple product of 8 fp8 per operand (uint2) into half2 accumulator.
__device__ __forceinline__ __half2 tp8(__half2 acc, uint2 A, uint2 B, uint2 C) {
    acc = __hfma2(__hmul2(cvt8(A.x & 0xFFFFu), cvt8(B.x & 0xFFFFu)),
                  cvt8(C.x & 0xFFFFu), acc);
    acc = __hfma2(__hmul2(cvt8(A.x >> 16), cvt8(B.x >> 16)),
                  cvt8(C.x >> 16), acc);
    acc = __hfma2(__hmul2(cvt8(A.y & 0xFFFFu), cvt8(B.y & 0xFFFFu)),
                  cvt8(C.y & 0xFFFFu), acc);
    acc = __hfma2(__hmul2(cvt8(A.y >> 16), cvt8(B.y >> 16)),
                  cvt8(C.y >> 16), acc);
    return acc;
}

// 16-fp8 triple product (uint4 chunks) into half2 accumulator.
__device__ __forceinline__ __half2 tp16(__half2 acc, uint4 A, uint4 B, uint4 C) {
    acc = tp8(acc, make_uint2(A.x, A.y), make_uint2(B.x, B.y), make_uint2(C.x, C.y));
    acc = tp8(acc, make_uint2(A.z, A.w), make_uint2(B.z, B.w), make_uint2(C.z, C.w));
    return acc;
}

// ---------------------------------------------------------------------------
// pass_a block work: 8 warps x 4 nnz (8-lane segments). Computes ONLY loss
// (deriv recomputed by pass_b; winners done in conv_win).
// ---------------------------------------------------------------------------
__device__ __forceinline__ void pass_a_work(
    int ablk,
    const int*   __restrict__ coo,
    const float* __restrict__ vals,
    float*       __restrict__ loss)
{
    int gw   = ablk * 8 + (threadIdx.x >> 5);   // < 125000 exact
    int lane = threadIdx.x & 31;
    int sg   = lane >> 3;
    int sl   = lane & 7;
    int n    = 4 * gw + sg;                     // < NNZ exact

    int c = (sl < 3) ? __ldg(coo + 3 * n + sl) : 0;
    int base = sg << 3;
    int s = __shfl_sync(0xffffffffu, c, base + 0);
    int r = __shfl_sync(0xffffffffu, c, base + 1);
    int o = __shfl_sync(0xffffffffu, c, base + 2);

    float val = __ldg(vals + n);

    const uint4* a0 = (const uint4*)(g_a8 + (size_t)s * ROW_B);
    const uint4* b1 = (const uint4*)(g_b8 + (size_t)r * ROW_B);
    const uint4* a2 = (const uint4*)(g_a8 + (size_t)o * ROW_B);

    const uint4 Z = make_uint4(0u, 0u, 0u, 0u);
    bool hi = (sl < 5);            // chunks 8..12 (13 data chunks total)

    uint4 x0 = __ldcg(a0 + sl);
    uint4 z0 = __ldcg(a2 + sl);
    uint4 y0 = __ldg (b1 + sl);
    uint4 x1 = hi ? __ldcg(a0 + 8 + sl) : Z;
    uint4 z1 = hi ? __ldcg(a2 + 8 + sl) : Z;
    uint4 y1 = hi ? __ldg (b1 + 8 + sl) : Z;

    __half2 acc = __float2half2_rn(0.0f);
    acc = tp16(acc, x0, y0, z0);
    acc = tp16(acc, x1, y1, z1);
    float2 f = __half22float2(acc);
    float sum = f.x + f.y;

    #pragma unroll
    for (int off = 4; off; off >>= 1)
        sum += __shfl_down_sync(0xffffffffu, sum, off, 8);

    if (sl == 0) {
        float diff = sum * INV_SCALE - val;
        __stcs(loss + n, diff * diff);
    }
}

// ---------------------------------------------------------------------------
// pass_b block work: 8 warps, one output row each. Winner rows recompute
// their deriv locally from the fp8 mirrors, then gather the two fp32 rows
// and write d*x*y. Self-resets winner slots for the next invocation.
// ---------------------------------------------------------------------------
__device__ __forceinline__ void pass_b_work(
    int bblk,
    const int*   __restrict__ coo,
    const float* __restrict__ vals,
    const float* __restrict__ a,
    const float* __restrict__ b,
    float*       __restrict__ grad_a,
    float*       __restrict__ grad_b)
{
    int warp = bblk * 8 + (threadIdx.x >> 5);
    int lane = threadIdx.x & 31;
    if (warp >= N_ENT + N_REL) return;

    float4* out;
    int k, n = 0;
    bool is_ent = (warp < N_ENT);

    if (is_ent) {
        out = (float4*)(grad_a + (size_t)warp * RANK);
        k = g_win_a[warp];
        if (k > 0 && lane == 0) g_win_a[warp] = 0;   // self-reset
    } else {
        out = (float4*)(grad_b + (size_t)(warp - N_ENT) * RANK);
        k = g_win_b[warp - N_ENT];
        if (k > 0 && lane == 0) g_win_b[warp - N_ENT] = 0;
    }

    if (k <= 0) {
        float4 z = make_float4(0.f, 0.f, 0.f, 0.f);
        #pragma unroll
        for (int it = 0; it < 2; it++) {
            int j = lane + it * 32;
            if (j < RV4) __stcs(out + j, z);
        }
        return;
    }

    bool is_obj = is_ent && (k > NNZ);
    n = is_obj ? (k - 1 - NNZ) : (k - 1);

    int s = __ldg(coo + 3 * n + 0);
    int r = __ldg(coo + 3 * n + 1);
    int o = __ldg(coo + 3 * n + 2);

    // Recompute deriv: fp8 dot over 25 active lanes, full-warp reduce.
    const uint2* pa0 = (const uint2*)(g_a8 + (size_t)s * ROW_B);
    const uint2* pb1 = (const uint2*)(g_b8 + (size_t)r * ROW_B);
    const uint2* pa2 = (const uint2*)(g_a8 + (size_t)o * ROW_B);
    bool act = (lane < DATA_U2);
    uint2 Zu = make_uint2(0u, 0u);
    uint2 A  = act ? __ldcg(pa0 + lane) : Zu;
    uint2 Bv = act ? __ldg (pb1 + lane) : Zu;
    uint2 C  = act ? __ldcg(pa2 + lane) : Zu;
    __half2 hacc = __float2half2_rn(0.0f);
    hacc = tp8(hacc, A, Bv, C);
    float2 hf = __half22float2(hacc);
    float sum = hf.x + hf.y;
    #pragma unroll
    for (int off = 16; off; off >>= 1)
        sum += __shfl_xor_sync(0xffffffffu, sum, off);
    float d = 2.0f * (sum * INV_SCALE - __ldg(vals + n));

    // Select the two fp32 factor rows.
    const float4* x;   // b-row where applicable (L1 path)
    const float4* y;
    bool x_is_b;
    if (is_ent) {
        x = (const float4*)(b + (size_t)r * RANK); x_is_b = true;
        y = (const float4*)(a + (size_t)(is_obj ? s : o) * RANK);
        // obj winner: g_c = d * a0 * b1 ; subj winner: g_a = d * b1 * a2
    } else {
        x = (const float4*)(a + (size_t)s * RANK); x_is_b = false;
        y = (const float4*)(a + (size_t)o * RANK);   // g_b = d * a0 * a2
    }

    #pragma unroll
    for (int it = 0; it < 2; it++) {
        int j = lane + it * 32;
        if (j < RV4) {
            float4 u = x_is_b ? __ldg(x + j) : __ldcg(x + j);
            float4 v = __ldcg(y + j);
            float4 w = make_float4(d * u.x * v.x, d * u.y * v.y,
                                   d * u.z * v.z, d * u.w * v.w);
            __stcs(out + j, w);
        }
    }
}

// ---------------------------------------------------------------------------
// Fused kernel (unchanged from R15 — measured 107us): pass_a and pass_b
// blocks interleaved proportionally so each wave carries both workloads.
// ---------------------------------------------------------------------------
__global__ void __launch_bounds__(256) fused_kernel(
    const int*   __restrict__ coo,
    const float* __restrict__ vals,
    const float* __restrict__ a,
    const float* __restrict__ b,
    float*       __restrict__ loss,
    float*       __restrict__ grad_a,
    float*       __restrict__ grad_b)
{
    int bid = blockIdx.x;
    long long t = (long long)bid * NA_BLOCKS;
    int lo = (int)(t / TOT_BLOCKS);
    int hi = (int)((t + NA_BLOCKS) / TOT_BLOCKS);
    if (hi > lo)
        pass_a_work(lo, coo, vals, loss);
    else
        pass_b_work(bid - hi, coo, vals, a, b, grad_a, grad_b);
}

// ---------------------------------------------------------------------------
// Launch. Inputs (metadata order): coo_ns int32 [NNZ,3], vals_ns f32 [NNZ],
// a f32 [N_ENT,RANK], b f32 [N_REL,RANK].
// Output: loss[NNZ] | grad_a[N_ENT*RANK] | grad_b[N_REL*RANK]  (f32).
// ---------------------------------------------------------------------------
extern "C" void kernel_launch(void* const* d_in, const int* in_sizes, int n_in,
                              void* d_out, int out_size)
{
    const int*   coo  = (const int*)d_in[0];
    const float* vals = (const float*)d_in[1];
    const float* a    = (const float*)d_in[2];
    const float* b    = (const float*)d_in[3];

    float* out    = (float*)d_out;
    float* loss   = out;
    float* grad_a = out + NNZ;
    float* grad_b = out + NNZ + (size_t)N_ENT * RANK;

    // fp8 mirror build + spread winner races
    conv_win_kernel<<<CONV_BLOCKS, 256>>>(a, b, coo);

    // fused loss + gradient kernel
    fused_kernel<<<TOT_BLOCKS, 256>>>(coo, vals, a, b, loss, grad_a, grad_b);
}

// round 17
// speedup vs baseline: 1.4690x; 1.4109x over previous
#include <cuda_runtime.h>
#include <cuda_fp16.h>
#include <cuda_fp8.h>
#include <cstdint>

#define RANK  200
#define NNZ   500000
#define N_ENT 200000
#define N_REL 500
#define RV4   (RANK / 4)   // 50 float4 per row (fp32 path)

#define ROW_B   224        // padded fp8 row bytes
#define ROW_U2  28         // uint2 groups per padded row
#define DATA_U2 25         // uint2 groups holding real data

#define SCALE_A 256.0f
#define SCALE_B 16.0f
#define INV_SCALE (1.0f / (SCALE_A * SCALE_A * SCALE_B))   // 2^-20, exact

// Fused-kernel block partition (Bresenham proportional interleave).
#define NA_BLOCKS 15625    // pass_a: 32 nnz/block (8 warps x 4 nnz) -> exact
#define NB_BLOCKS 25063    // pass_b: 8 rows/block over N_ENT+N_REL=200500
#define TOT_BLOCKS (NA_BLOCKS + NB_BLOCKS)

// conv kernel geometry
#define NAG (N_ENT * ROW_U2)          // 5,600,000 conv threads for a
#define NBG (N_REL * ROW_U2)          // 14,000 conv threads for b
#define CONV_BLOCKS ((NAG + NBG + 255) / 256)   // 21,930
#define WIN_PER_BLOCK 23              // 21,930 * 23 = 504,390 >= NNZ
#define HIST_BLOCKS 148               // g_win_b smem-aggregation blocks

// Scratch (__device__ globals: zero-initialized at load; conv fully rewrites
// the mirrors, winner slots are self-reset by the consumer, so every
// invocation — correctness run and each graph replay — starts identically).
__device__ int g_win_a[N_ENT];   // winner key: n+1 (subj) or n+1+NNZ (obj); 0 = none
__device__ int g_win_b[N_REL];   // winner key: n+1; 0 = none
__device__ __align__(16) uint8_t g_a8[(size_t)N_ENT * ROW_B]; // e4m3(a*256), 44.8 MB
__device__ __align__(16) uint8_t g_b8[(size_t)N_REL * ROW_B]; // e4m3(b*16), 112 KB

// ---------------------------------------------------------------------------
// Kernel 1: fp8 mirror build + winner races, atomic-count-minimized.
// R15/R16 measured a hard global-atomic throughput wall (~17 ops/cyc chip-
// wide), so the g_win_b stream (500K atomics over just 500 slots) is reduced
// via per-block SMEM max tables in HIST_BLOCKS dedicated blocks (global
// atomics: 500K -> ~64K). g_win_a (1M atomics over 200K spread slots) cannot
// be smem-aggregated and stays spread across the conv blocks.
// Winner-key encoding reproduces XLA sequential-scatter semantics: obj
// writes (.set applied second) beat subj writes (key n+1+NNZ vs n+1);
// within a class, higher nnz index wins (last update wins).
// ---------------------------------------------------------------------------
__device__ __forceinline__ uint32_t pack4_e4m3(float4 v, float s) {
    __nv_fp8x2_storage_t lo = __nv_cvt_float2_to_fp8x2(
        make_float2(v.x * s, v.y * s), __NV_SATFINITE, __NV_E4M3);
    __nv_fp8x2_storage_t hi = __nv_cvt_float2_to_fp8x2(
        make_float2(v.z * s, v.w * s), __NV_SATFINITE, __NV_E4M3);
    return (uint32_t)lo | ((uint32_t)hi << 16);
}

__global__ void __launch_bounds__(256) conv_win_kernel(
    const float* __restrict__ a,
    const float* __restrict__ b,
    const int*   __restrict__ coo)
{
    __shared__ int sh[N_REL];

    if (blockIdx.x >= CONV_BLOCKS) {
        // ---- g_win_b hist block: smem-aggregated relation winner ----
        int hb = blockIdx.x - CONV_BLOCKS;
        for (int i = threadIdx.x; i < N_REL; i += 256) sh[i] = 0;
        __syncthreads();
        const int per = (NNZ + HIST_BLOCKS - 1) / HIST_BLOCKS;
        int lo = hb * per;
        int hi = lo + per; if (hi > NNZ) hi = NNZ;
        for (int n = lo + threadIdx.x; n < hi; n += 256) {
            int r = __ldg(coo + 3 * n + 1);
            atomicMax(&sh[r], n + 1);          // smem: spread, cheap
        }
        __syncthreads();
        for (int r = threadIdx.x; r < N_REL; r += 256) {
            int v = sh[r];
            if (v) atomicMax(&g_win_b[r], v);  // <=500 global atomics/block
        }
        return;
    }

    // ---- g_win_a winner races, spread: 23 nnz per block, 2 atomics each ----
    {
        int n = blockIdx.x * WIN_PER_BLOCK + threadIdx.x;
        if (threadIdx.x < WIN_PER_BLOCK && n < NNZ) {
            int s = __ldg(coo + 3 * n + 0);
            int o = __ldg(coo + 3 * n + 2);
            atomicMax(&g_win_a[s], n + 1);        // subj class
            atomicMax(&g_win_a[o], n + 1 + NNZ);  // obj class (beats subj)
        }
    }

    // ---- fp8 mirror build ----
    int i = blockIdx.x * blockDim.x + threadIdx.x;
    if (i < NAG) {
        int row = i / ROW_U2;
        int idx = i - row * ROW_U2;
        uint2 p = make_uint2(0u, 0u);
        if (idx < DATA_U2) {
            const float4* src = (const float4*)a + (size_t)row * RV4 + 2 * idx;
            p.x = pack4_e4m3(__ldcs(src),     SCALE_A);
            p.y = pack4_e4m3(__ldcs(src + 1), SCALE_A);
        }
        ((uint2*)g_a8)[i] = p;
    } else if (i < NAG + NBG) {
        int j = i - NAG;
        int row = j / ROW_U2;
        int idx = j - row * ROW_U2;
        uint2 p = make_uint2(0u, 0u);
        if (idx < DATA_U2) {
            const float4* src = (const float4*)b + (size_t)row * RV4 + 2 * idx;
            p.x = pack4_e4m3(__ldcs(src),     SCALE_B);
            p.y = pack4_e4m3(__ldcs(src + 1), SCALE_B);
        }
        ((uint2*)g_b8)[j] = p;
    }
}

// fp8x2 (low 16 bits) -> half2
__device__ __forceinline__ __half2 cvt8(uint32_t u) {
    __half2_raw hr = __nv_cvt_fp8x2_to_halfraw2((__nv_fp8x2_storage_t)u, __NV_E4M3);
    return *(__half2*)&hr;
}

// Triple product of 8 fp8 per operand (uint2) into half2 accumulator.
__device__ __forceinline__ __half2 tp8(__half2 acc, uint2 A, uint2 B, uint2 C) {
    acc = __hfma2(__hmul2(cvt8(A.x & 0xFFFFu), cvt8(B.x & 0xFFFFu)),
                  cvt8(C.x & 0xFFFFu), acc);
    acc = __hfma2(__hmul2(cvt8(A.x >> 16), cvt8(B.x >> 16)),
                  cvt8(C.x >> 16), acc);
    acc = __hfma2(__hmul2(cvt8(A.y & 0xFFFFu), cvt8(B.y & 0xFFFFu)),
                  cvt8(C.y & 0xFFFFu), acc);
    acc = __hfma2(__hmul2(cvt8(A.y >> 16), cvt8(B.y >> 16)),
                  cvt8(C.y >> 16), acc);
    return acc;
}

// 16-fp8 triple product (uint4 chunks) into half2 accumulator.
__device__ __forceinline__ __half2 tp16(__half2 acc, uint4 A, uint4 B, uint4 C) {
    acc = tp8(acc, make_uint2(A.x, A.y), make_uint2(B.x, B.y), make_uint2(C.x, C.y));
    acc = tp8(acc, make_uint2(A.z, A.w), make_uint2(B.z, B.w), make_uint2(C.z, C.w));
    return acc;
}

// ---------------------------------------------------------------------------
// pass_a block work: 8 warps x 4 nnz (8-lane segments). Computes ONLY loss
// (deriv recomputed by pass_b; winners done in conv_win).
// ---------------------------------------------------------------------------
__device__ __forceinline__ void pass_a_work(
    int ablk,
    const int*   __restrict__ coo,
    const float* __restrict__ vals,
    float*       __restrict__ loss)
{
    int gw   = ablk * 8 + (threadIdx.x >> 5);   // < 125000 exact
    int lane = threadIdx.x & 31;
    int sg   = lane >> 3;
    int sl   = lane & 7;
    int n    = 4 * gw + sg;                     // < NNZ exact

    int c = (sl < 3) ? __ldg(coo + 3 * n + sl) : 0;
    int base = sg << 3;
    int s = __shfl_sync(0xffffffffu, c, base + 0);
    int r = __shfl_sync(0xffffffffu, c, base + 1);
    int o = __shfl_sync(0xffffffffu, c, base + 2);

    float val = __ldg(vals + n);

    const uint4* a0 = (const uint4*)(g_a8 + (size_t)s * ROW_B);
    const uint4* b1 = (const uint4*)(g_b8 + (size_t)r * ROW_B);
    const uint4* a2 = (const uint4*)(g_a8 + (size_t)o * ROW_B);

    const uint4 Z = make_uint4(0u, 0u, 0u, 0u);
    bool hi = (sl < 5);            // chunks 8..12 (13 data chunks total)

    uint4 x0 = __ldcg(a0 + sl);
    uint4 z0 = __ldcg(a2 + sl);
    uint4 y0 = __ldg (b1 + sl);
    uint4 x1 = hi ? __ldcg(a0 + 8 + sl) : Z;
    uint4 z1 = hi ? __ldcg(a2 + 8 + sl) : Z;
    uint4 y1 = hi ? __ldg (b1 + 8 + sl) : Z;

    __half2 acc = __float2half2_rn(0.0f);
    acc = tp16(acc, x0, y0, z0);
    acc = tp16(acc, x1, y1, z1);
    float2 f = __half22float2(acc);
    float sum = f.x + f.y;

    #pragma unroll
    for (int off = 4; off; off >>= 1)
        sum += __shfl_down_sync(0xffffffffu, sum, off, 8);

    if (sl == 0) {
        float diff = sum * INV_SCALE - val;
        __stcs(loss + n, diff * diff);
    }
}

// ---------------------------------------------------------------------------
// pass_b block work: 8 warps, one output row each. Winner rows recompute
// their deriv locally from the fp8 mirrors, then gather the two fp32 rows
// and write d*x*y. Self-resets winner slots for the next invocation.
// ---------------------------------------------------------------------------
__device__ __forceinline__ void pass_b_work(
    int bblk,
    const int*   __restrict__ coo,
    const float* __restrict__ vals,
    const float* __restrict__ a,
    const float* __restrict__ b,
    float*       __restrict__ grad_a,
    float*       __restrict__ grad_b)
{
    int warp = bblk * 8 + (threadIdx.x >> 5);
    int lane = threadIdx.x & 31;
    if (warp >= N_ENT + N_REL) return;

    float4* out;
    int k, n = 0;
    bool is_ent = (warp < N_ENT);

    if (is_ent) {
        out = (float4*)(grad_a + (size_t)warp * RANK);
        k = g_win_a[warp];
        if (k > 0 && lane == 0) g_win_a[warp] = 0;   // self-reset
    } else {
        out = (float4*)(grad_b + (size_t)(warp - N_ENT) * RANK);
        k = g_win_b[warp - N_ENT];
        if (k > 0 && lane == 0) g_win_b[warp - N_ENT] = 0;
    }

    if (k <= 0) {
        float4 z = make_float4(0.f, 0.f, 0.f, 0.f);
        #pragma unroll
        for (int it = 0; it < 2; it++) {
            int j = lane + it * 32;
            if (j < RV4) __stcs(out + j, z);
        }
        return;
    }

    bool is_obj = is_ent && (k > NNZ);
    n = is_obj ? (k - 1 - NNZ) : (k - 1);

    int s = __ldg(coo + 3 * n + 0);
    int r = __ldg(coo + 3 * n + 1);
    int o = __ldg(coo + 3 * n + 2);

    // Recompute deriv: fp8 dot over 25 active lanes, full-warp reduce.
    const uint2* pa0 = (const uint2*)(g_a8 + (size_t)s * ROW_B);
    const uint2* pb1 = (const uint2*)(g_b8 + (size_t)r * ROW_B);
    const uint2* pa2 = (const uint2*)(g_a8 + (size_t)o * ROW_B);
    bool act = (lane < DATA_U2);
    uint2 Zu = make_uint2(0u, 0u);
    uint2 A  = act ? __ldcg(pa0 + lane) : Zu;
    uint2 Bv = act ? __ldg (pb1 + lane) : Zu;
    uint2 C  = act ? __ldcg(pa2 + lane) : Zu;
    __half2 hacc = __float2half2_rn(0.0f);
    hacc = tp8(hacc, A, Bv, C);
    float2 hf = __half22float2(hacc);
    float sum = hf.x + hf.y;
    #pragma unroll
    for (int off = 16; off; off >>= 1)
        sum += __shfl_xor_sync(0xffffffffu, sum, off);
    float d = 2.0f * (sum * INV_SCALE - __ldg(vals + n));

    // Select the two fp32 factor rows.
    const float4* x;   // b-row where applicable (L1 path)
    const float4* y;
    bool x_is_b;
    if (is_ent) {
        x = (const float4*)(b + (size_t)r * RANK); x_is_b = true;
        y = (const float4*)(a + (size_t)(is_obj ? s : o) * RANK);
        // obj winner: g_c = d * a0 * b1 ; subj winner: g_a = d * b1 * a2
    } else {
        x = (const float4*)(a + (size_t)s * RANK); x_is_b = false;
        y = (const float4*)(a + (size_t)o * RANK);   // g_b = d * a0 * a2
    }

    #pragma unroll
    for (int it = 0; it < 2; it++) {
        int j = lane + it * 32;
        if (j < RV4) {
            float4 u = x_is_b ? __ldg(x + j) : __ldcg(x + j);
            float4 v = __ldcg(y + j);
            float4 w = make_float4(d * u.x * v.x, d * u.y * v.y,
                                   d * u.z * v.z, d * u.w * v.w);
            __stcs(out + j, w);
        }
    }
}

// ---------------------------------------------------------------------------
// Fused kernel (unchanged — measured ~108us twice): pass_a and pass_b
// blocks interleaved proportionally so each wave carries both workloads.
// ---------------------------------------------------------------------------
__global__ void __launch_bounds__(256) fused_kernel(
    const int*   __restrict__ coo,
    const float* __restrict__ vals,
    const float* __restrict__ a,
    const float* __restrict__ b,
    float*       __restrict__ loss,
    float*       __restrict__ grad_a,
    float*       __restrict__ grad_b)
{
    int bid = blockIdx.x;
    long long t = (long long)bid * NA_BLOCKS;
    int lo = (int)(t / TOT_BLOCKS);
    int hi = (int)((t + NA_BLOCKS) / TOT_BLOCKS);
    if (hi > lo)
        pass_a_work(lo, coo, vals, loss);
    else
        pass_b_work(bid - hi, coo, vals, a, b, grad_a, grad_b);
}

// ---------------------------------------------------------------------------
// Launch. Inputs (metadata order): coo_ns int32 [NNZ,3], vals_ns f32 [NNZ],
// a f32 [N_ENT,RANK], b f32 [N_REL,RANK].
// Output: loss[NNZ] | grad_a[N_ENT*RANK] | grad_b[N_REL*RANK]  (f32).
// ---------------------------------------------------------------------------
extern "C" void kernel_launch(void* const* d_in, const int* in_sizes, int n_in,
                              void* d_out, int out_size)
{
    const int*   coo  = (const int*)d_in[0];
    const float* vals = (const float*)d_in[1];
    const float* a    = (const float*)d_in[2];
    const float* b    = (const float*)d_in[3];

    float* out    = (float*)d_out;
    float* loss   = out;
    float* grad_a = out + NNZ;
    float* grad_b = out + NNZ + (size_t)N_ENT * RANK;

    // fp8 mirror build + spread g_win_a races + smem-aggregated g_win_b
    conv_win_kernel<<<CONV_BLOCKS + HIST_BLOCKS, 256>>>(a, b, coo);

    // fused loss + gradient kernel
    fused_kernel<<<TOT_BLOCKS, 256>>>(coo, vals, a, b, loss, grad_a, grad_b);
}